// round 14
// baseline (speedup 1.0000x reference)
#include <cuda_runtime.h>
#include <cuda_bf16.h>
#include <cstdint>

// Problem constants
constexpr int B = 128, L = 1024, V = 512, H = 512, C = 20;
constexpr int NROW = L * B;        // 131072

// ---------------------------------------------------------------------------
// Device scratch
// ---------------------------------------------------------------------------
__device__ float g_T[3][V][H];                         // transposed conv weights
__device__ __nv_bfloat16 g_yB[(size_t)NROW * H];       // conv output (bf16)
__device__ float g_h[2][B * H];                        // final hidden (fp32, classifier)
__device__ __nv_bfloat16 g_hB[2][B * H];               // hidden state (bf16, exchange)
constexpr int NGRP = 8, GRP = 16;                      // 8 row-groups x 16 dim CTAs
__device__ unsigned g_gcnt[NGRP];
__device__ unsigned g_ggen[NGRP];

// ---------------------------------------------------------------------------
// Helpers
// ---------------------------------------------------------------------------
__device__ __forceinline__ void mma_bf16(float c[4], const uint32_t a[4], const uint32_t b[2]) {
    asm volatile(
        "mma.sync.aligned.m16n8k16.row.col.f32.bf16.bf16.f32 "
        "{%0,%1,%2,%3}, {%4,%5,%6,%7}, {%8,%9}, {%0,%1,%2,%3};\n"
        : "+f"(c[0]), "+f"(c[1]), "+f"(c[2]), "+f"(c[3])
        : "r"(a[0]), "r"(a[1]), "r"(a[2]), "r"(a[3]), "r"(b[0]), "r"(b[1]));
}

__device__ __forceinline__ void cp16(void* dst_smem, const void* src) {
    uint32_t d = (uint32_t)__cvta_generic_to_shared(dst_smem);
    asm volatile("cp.async.cg.shared.global [%0], [%1], 16;" :: "r"(d), "l"(src));
}
#define CP_COMMIT()  asm volatile("cp.async.commit_group;" ::: "memory")
#define CP_WAIT0()   asm volatile("cp.async.wait_group 0;" ::: "memory")

// ---------------------------------------------------------------------------
// Init (runs every launch — graph replays)
// ---------------------------------------------------------------------------
__global__ void init_kernel() {
    const int i = blockIdx.x * blockDim.x + threadIdx.x;
    if (i < 2 * B * H) {
        ((float*)g_h)[i] = 0.0f;
        ((__nv_bfloat16*)g_hB)[i] = __float2bfloat16(0.0f);
    }
    if (i < NGRP) { g_gcnt[i] = 0u; g_ggen[i] = 0u; }
}

// ---------------------------------------------------------------------------
// Prep: transpose conv_w -> g_T
// ---------------------------------------------------------------------------
__global__ void prep_kernel(const float* __restrict__ conv_w) {
    const int idx = blockIdx.x * blockDim.x + threadIdx.x;
    if (idx < H * V * 3) {
        const int k = idx % 3;
        const int v = (idx / 3) % V;
        const int h = idx / (3 * V);
        g_T[k][v][h] = conv_w[idx];
    }
}

// ---------------------------------------------------------------------------
// Embedding "conv" -> bf16 y
// ---------------------------------------------------------------------------
__global__ void embed_kernel(const int* __restrict__ x, const float* __restrict__ conv_b) {
    const int n = blockIdx.x;      // n = t*B + b
    const int t = n >> 7;
    const int b = n & 127;
    const int x0 = x[b * L + t];
    const int xm = (t > 0) ? x[b * L + t - 1] : -1;
    const int xp = (t < L - 1) ? x[b * L + t + 1] : -1;
    const int hb = threadIdx.x * 4;

    float4 acc = *(const float4*)(conv_b + hb);
    {
        const float4 e = *(const float4*)(&g_T[1][x0][hb]);
        acc.x += e.x; acc.y += e.y; acc.z += e.z; acc.w += e.w;
    }
    if (xm >= 0) {
        const float4 e = *(const float4*)(&g_T[0][xm][hb]);
        acc.x += e.x; acc.y += e.y; acc.z += e.z; acc.w += e.w;
    }
    if (xp >= 0) {
        const float4 e = *(const float4*)(&g_T[2][xp][hb]);
        acc.x += e.x; acc.y += e.y; acc.z += e.z; acc.w += e.w;
    }
    __nv_bfloat162 p0, p1;
    p0.x = __float2bfloat16_rn(fmaxf(acc.x, 0.0f));
    p0.y = __float2bfloat16_rn(fmaxf(acc.y, 0.0f));
    p1.x = __float2bfloat16_rn(fmaxf(acc.z, 0.0f));
    p1.y = __float2bfloat16_rn(fmaxf(acc.w, 0.0f));
    *(__nv_bfloat162*)(g_yB + (size_t)n * H + hb) = p0;
    *(__nv_bfloat162*)(g_yB + (size_t)n * H + hb + 2) = p1;
}

// ---------------------------------------------------------------------------
// Fused persistent GRU kernel v14 = v13 + (single-pass 2-plane Red,
// end-of-step y cp.async, partial w_ih register cache).
// Warp (nt, kh): nt=warp>>1 owns cols nt*24..+23, kh=warp&1 owns K-half.
// Step: [top: wait y-cp + sync] [gi mma (6 reg-cached + 10 smem chunks)]
//       [tid0 spin] [sync] [cp h] [cp-wait + sync] [gh mma (reg weights)]
//       [sync] [Red: both kh planes, single write] [sync]
//       [gates: sum 2 planes + h STG] [sync] [y(t+1) cp + release].
// Red aliases over the y+h tile region (reads of both complete beforehand).
// ---------------------------------------------------------------------------
constexpr int WHH_OFF = 96 * 256;            // 24576 words
constexpr int YOFF = 2 * 96 * 256;           // 49152
constexpr int HOFF = YOFF + 4096;            // 53248
constexpr int GRU_SMEM = (HOFF + 4096) * 4;  // 229,376 B
constexpr int RLD = 164;                     // Red row stride (floats)
constexpr int RPLANE = 16 * RLD;             // per-kh plane (floats)
constexpr int NCACHE = 6;                    // w_ih reg-cached chunks

__global__ void __launch_bounds__(256, 1) gru_kernel(const float* __restrict__ w_ih,
                                                     const float* __restrict__ w_hh,
                                                     const float* __restrict__ b_ih,
                                                     const float* __restrict__ b_hh) {
    extern __shared__ uint32_t smw[];
    float* Red = (float*)(smw + YOFF);       // 2 planes aliased over y+h tiles

    const int tid = threadIdx.x, warp = tid >> 5, lane = tid & 31;
    const int g = lane >> 2, tig = lane & 3;
    const int nt = warp >> 1, kh = warp & 1;
    const int rg = blockIdx.x >> 4, dg = blockIdx.x & 15;
    const int pr = tid >> 4, ps = tid & 15;  // cp/sts row + 16-word segment

    // Prologue: y(0) via cp.async
    {
        const __nv_bfloat16* src = g_yB + (size_t)(rg * 16 + pr) * H + ps * 32;
#pragma unroll
        for (int i = 0; i < 4; i++) {
            const int w0 = ps * 16 + 4 * i;
            cp16(smw + YOFF + pr * 256 + (w0 ^ ((pr & 7) << 2)), src + i * 8);
        }
        CP_COMMIT();
    }

    // Weights -> SMEM bf16 with XOR swizzle
    for (int i = tid; i < 2 * 96 * 128; i += 256) {
        const int mat = i / (96 * 128);
        const int rem = i - mat * (96 * 128);
        const int n = rem >> 7, f4 = rem & 127;
        const int tt = n >> 3;
        const int grow = (tt % 3) * H + dg * 32 + (tt / 3) * 8 + (n & 7);
        const float* srcm = mat ? w_hh : w_ih;
        const float4 v = *(const float4*)(srcm + (size_t)grow * H + f4 * 4);
        __nv_bfloat162 q0, q1;
        q0.x = __float2bfloat16_rn(v.x); q0.y = __float2bfloat16_rn(v.y);
        q1.x = __float2bfloat16_rn(v.z); q1.y = __float2bfloat16_rn(v.w);
        const int w0 = (f4 * 2) ^ ((n & 7) << 2);
        uint2 pk;
        pk.x = *(const uint32_t*)&q0;
        pk.y = *(const uint32_t*)&q1;
        *(uint2*)(smw + mat * WHH_OFF + n * 256 + w0) = pk;
    }

    // Gate-phase setup: thread -> (row_e, dim pair j2)
    const int row_e = tid >> 4;
    const int j2 = (tid & 15) * 2;
    const int grow_e = rg * 16 + row_e;
    const int jg = dg * 32 + j2;
    float2 br2, bz2;
    {
        float2 a = *(const float2*)(b_ih + jg), b = *(const float2*)(b_hh + jg);
        br2 = make_float2(a.x + b.x, a.y + b.y);
        a = *(const float2*)(b_ih + H + jg); b = *(const float2*)(b_hh + H + jg);
        bz2 = make_float2(a.x + b.x, a.y + b.y);
    }
    const float2 bin2 = *(const float2*)(b_ih + 2 * H + jg);
    const float2 bhn2 = *(const float2*)(b_hh + 2 * H + jg);

    // Fragment bases
    const uint32_t* Yb0 = smw + YOFF + g * 256;
    const uint32_t* Yb1 = smw + YOFF + (g + 8) * 256;
    const uint32_t* Hb0 = smw + HOFF + g * 256;
    const uint32_t* Hb1 = smw + HOFF + (g + 8) * 256;
    const uint32_t* Wi0 = smw + (nt * 24 + g) * 256;
    const uint32_t* Wh0 = smw + WHH_OFF + (nt * 24 + g) * 256;
    const int xw = g << 2;
    const int kbase = kh * 128;

    __syncthreads();

    // w_hh b-fragments -> registers (all 16 chunks; reused 1024 steps)
    uint32_t breg[16][3][2];
#pragma unroll
    for (int ck = 0; ck < 16; ck++) {
        const int w = kbase + ck * 8 + tig;
        const int wx0 = w ^ xw;
        const int wx4 = (w + 4) ^ xw;
        breg[ck][0][0] = Wh0[wx0];            breg[ck][0][1] = Wh0[wx4];
        breg[ck][1][0] = Wh0[8 * 256 + wx0];  breg[ck][1][1] = Wh0[8 * 256 + wx4];
        breg[ck][2][0] = Wh0[16 * 256 + wx0]; breg[ck][2][1] = Wh0[16 * 256 + wx4];
    }
    // w_ih b-fragments for the first NCACHE chunks
    uint32_t bregI[NCACHE][3][2];
#pragma unroll
    for (int ck = 0; ck < NCACHE; ck++) {
        const int w = kbase + ck * 8 + tig;
        const int wx0 = w ^ xw;
        const int wx4 = (w + 4) ^ xw;
        bregI[ck][0][0] = Wi0[wx0];            bregI[ck][0][1] = Wi0[wx4];
        bregI[ck][1][0] = Wi0[8 * 256 + wx0];  bregI[ck][1][1] = Wi0[8 * 256 + wx4];
        bregI[ck][2][0] = Wi0[16 * 256 + wx0]; bregI[ck][2][1] = Wi0[16 * 256 + wx4];
    }

    float2 ho2 = make_float2(0.0f, 0.0f);   // h_old lives in registers
    int p = 0;
    for (int t = 0; t < L; t++) {
        const bool hasnext = (t + 1 < L);

        // ---- top: y(t) cp (committed at end of prev step / prologue) done ----
        CP_WAIT0();
        __syncthreads();

        // ---- gi mma: y(t) x w_ih ----
        float c0[4] = {}, c1[4] = {}, c2i[4] = {}, c2h[4] = {};
#pragma unroll
        for (int ck = 0; ck < NCACHE; ck++) {
            const int w = kbase + ck * 8 + tig;
            const int wx0 = w ^ xw;
            const int wx4 = (w + 4) ^ xw;
            uint32_t ay[4];
            ay[0] = Yb0[wx0]; ay[1] = Yb1[wx0]; ay[2] = Yb0[wx4]; ay[3] = Yb1[wx4];
            mma_bf16(c0, ay, bregI[ck][0]);
            mma_bf16(c1, ay, bregI[ck][1]);
            mma_bf16(c2i, ay, bregI[ck][2]);
        }
#pragma unroll 5
        for (int ck = NCACHE; ck < 16; ck++) {
            const int w = kbase + ck * 8 + tig;
            const int wx0 = w ^ xw;
            const int wx4 = (w + 4) ^ xw;
            uint32_t ay[4], bb[2];
            ay[0] = Yb0[wx0]; ay[1] = Yb1[wx0]; ay[2] = Yb0[wx4]; ay[3] = Yb1[wx4];
            bb[0] = Wi0[wx0]; bb[1] = Wi0[wx4];
            mma_bf16(c0, ay, bb);
            bb[0] = Wi0[8 * 256 + wx0]; bb[1] = Wi0[8 * 256 + wx4];
            mma_bf16(c1, ay, bb);
            bb[0] = Wi0[16 * 256 + wx0]; bb[1] = Wi0[16 * 256 + wx4];
            mma_bf16(c2i, ay, bb);
        }

        // ---- wait: h(t) epoch visible (tid0 spin; merged barrier) ----
        if (tid == 0) {
            unsigned v;
            do {
                asm volatile("ld.acquire.gpu.u32 %0, [%1];" : "=r"(v) : "l"(g_ggen + rg) : "memory");
            } while (v < (unsigned)t);
        }
        __syncthreads();   // gi reads done (all warps) + h published

        // ---- cp h(t) tile ----
        {
            const __nv_bfloat16* src = g_hB[p] + (size_t)(rg * 16 + pr) * H + ps * 32;
#pragma unroll
            for (int i = 0; i < 4; i++) {
                const int w0 = ps * 16 + 4 * i;
                cp16(smw + HOFF + pr * 256 + (w0 ^ ((pr & 7) << 2)), src + i * 8);
            }
            CP_COMMIT();
        }
        CP_WAIT0();
        __syncthreads();

        // ---- gh mma: h(t) x w_hh (weights from registers) ----
#pragma unroll
        for (int ck = 0; ck < 16; ck++) {
            const int w = kbase + ck * 8 + tig;
            const int wx0 = w ^ xw;
            const int wx4 = (w + 4) ^ xw;
            uint32_t ah[4];
            ah[0] = Hb0[wx0]; ah[1] = Hb1[wx0]; ah[2] = Hb0[wx4]; ah[3] = Hb1[wx4];
            mma_bf16(c0, ah, breg[ck][0]);
            mma_bf16(c1, ah, breg[ck][1]);
            mma_bf16(c2h, ah, breg[ck][2]);
        }
        __syncthreads();   // y+h tile reads done -> Red planes may overwrite

        // ---- single Red write pass: each kh warp writes its own plane ----
        {
            float* Ra = Red + kh * RPLANE + g * RLD;
            float* Rb = Red + kh * RPLANE + (g + 8) * RLD;
            const int n0 = nt * 24 + 2 * tig;
            const int nd = nt * 8 + 2 * tig;
            *(float2*)&Ra[n0] = make_float2(c0[0], c0[1]);
            *(float2*)&Rb[n0] = make_float2(c0[2], c0[3]);
            *(float2*)&Ra[n0 + 8] = make_float2(c1[0], c1[1]);
            *(float2*)&Rb[n0 + 8] = make_float2(c1[2], c1[3]);
            *(float2*)&Ra[96 + nd] = make_float2(c2i[0], c2i[1]);
            *(float2*)&Rb[96 + nd] = make_float2(c2i[2], c2i[3]);
            *(float2*)&Ra[128 + nd] = make_float2(c2h[0], c2h[1]);
            *(float2*)&Rb[128 + nd] = make_float2(c2h[2], c2h[3]);
        }
        __syncthreads();

        // ---- gates: sum the two kh planes; h_old from registers ----
        {
            const float* R0 = Red + row_e * RLD;
            const float* R1 = Red + RPLANE + row_e * RLD;
            const int rcol = (j2 >> 3) * 24 + (j2 & 7);
            const float2 rpa = *(const float2*)&R0[rcol],      rpb = *(const float2*)&R1[rcol];
            const float2 zpa = *(const float2*)&R0[rcol + 8],  zpb = *(const float2*)&R1[rcol + 8];
            const float2 nia = *(const float2*)&R0[96 + j2],   nib = *(const float2*)&R1[96 + j2];
            const float2 nha = *(const float2*)&R0[128 + j2],  nhb = *(const float2*)&R1[128 + j2];
            const float r0 = 1.0f / (1.0f + __expf(-(rpa.x + rpb.x + br2.x)));
            const float r1 = 1.0f / (1.0f + __expf(-(rpa.y + rpb.y + br2.y)));
            const float z0 = 1.0f / (1.0f + __expf(-(zpa.x + zpb.x + bz2.x)));
            const float z1 = 1.0f / (1.0f + __expf(-(zpa.y + zpb.y + bz2.y)));
            const float n0v = tanhf(nia.x + nib.x + bin2.x + r0 * (nha.x + nhb.x + bhn2.x));
            const float n1v = tanhf(nia.y + nib.y + bin2.y + r1 * (nha.y + nhb.y + bhn2.y));
            float2 hn;
            hn.x = (1.0f - z0) * n0v + z0 * ho2.x;
            hn.y = (1.0f - z1) * n1v + z1 * ho2.y;
            ho2 = hn;
            __nv_bfloat162 hb;
            hb.x = __float2bfloat16_rn(hn.x);
            hb.y = __float2bfloat16_rn(hn.y);
            *(__nv_bfloat162*)(g_hB[p ^ 1] + (size_t)grow_e * H + jg) = hb;
            if (t == L - 1) *(float2*)(g_h[0] + (size_t)grow_e * H + jg) = hn;
        }

        __syncthreads();   // Red reads + h STG done

        // ---- y(t+1) cp into y tile (overlaps release + next spin) ----
        if (hasnext) {
            const __nv_bfloat16* src = g_yB + (size_t)((t + 1) * B + rg * 16 + pr) * H + ps * 32;
#pragma unroll
            for (int i = 0; i < 4; i++) {
                const int w0 = ps * 16 + 4 * i;
                cp16(smw + YOFF + pr * 256 + (w0 ^ ((pr & 7) << 2)), src + i * 8);
            }
        }
        CP_COMMIT();

        // ---- release-arrive: h(t+1) published ----
        if (tid == 0) {
            unsigned old;
            asm volatile("atom.release.gpu.global.add.u32 %0, [%1], 1;"
                         : "=r"(old) : "l"(g_gcnt + rg) : "memory");
            if (old == GRP - 1) {
                g_gcnt[rg] = 0u;
                const unsigned tgt = (unsigned)(t + 1);
                asm volatile("st.release.gpu.global.u32 [%0], %1;"
                             :: "l"(g_ggen + rg), "r"(tgt) : "memory");
            }
        }
        p ^= 1;
    }
}

// ---------------------------------------------------------------------------
// Classifier
// ---------------------------------------------------------------------------
__global__ void classifier_kernel(const float* __restrict__ cls_w,
                                  const float* __restrict__ cls_b,
                                  float* __restrict__ out) {
    const int b = blockIdx.x / C;
    const int cc = blockIdx.x % C;
    const float* h = g_h[0] + b * H;
    const float* w = cls_w + cc * H;
    float s = 0.0f;
    for (int k = threadIdx.x; k < H; k += 64) s += h[k] * w[k];
#pragma unroll
    for (int o = 16; o > 0; o >>= 1) s += __shfl_down_sync(0xffffffffu, s, o);
    __shared__ float red[2];
    if ((threadIdx.x & 31) == 0) red[threadIdx.x >> 5] = s;
    __syncthreads();
    if (threadIdx.x == 0) out[b * C + cc] = red[0] + red[1] + cls_b[cc];
}

// ---------------------------------------------------------------------------
// Launch
// ---------------------------------------------------------------------------
extern "C" void kernel_launch(void* const* d_in, const int* in_sizes, int n_in,
                              void* d_out, int out_size) {
    const int*   x      = (const int*)d_in[0];
    const float* conv_w = (const float*)d_in[1];
    const float* conv_b = (const float*)d_in[2];
    const float* w_ih   = (const float*)d_in[3];
    const float* w_hh   = (const float*)d_in[4];
    const float* b_ih   = (const float*)d_in[5];
    const float* b_hh   = (const float*)d_in[6];
    const float* cls_w  = (const float*)d_in[7];
    const float* cls_b  = (const float*)d_in[8];
    float* out = (float*)d_out;

    cudaFuncSetAttribute(gru_kernel, cudaFuncAttributeMaxDynamicSharedMemorySize, GRU_SMEM);

    init_kernel<<<512, 256>>>();
    prep_kernel<<<(H * V * 3 + 255) / 256, 256>>>(conv_w);
    embed_kernel<<<NROW, 128>>>(x, conv_b);
    gru_kernel<<<NGRP * GRP, 256, GRU_SMEM>>>(w_ih, w_hh, b_ih, b_hh);
    classifier_kernel<<<B * C, 64>>>(cls_w, cls_b, out);
}

// round 15
// speedup vs baseline: 1.2511x; 1.2511x over previous
#include <cuda_runtime.h>
#include <cuda_bf16.h>
#include <cstdint>

// Problem constants
constexpr int B = 128, L = 1024, V = 512, H = 512, C = 20;
constexpr int NROW = L * B;        // 131072

// ---------------------------------------------------------------------------
// Device scratch
// ---------------------------------------------------------------------------
__device__ float g_T[3][V][H];                         // transposed conv weights
__device__ __nv_bfloat16 g_yB[(size_t)NROW * H];       // conv output (bf16)
__device__ float g_h[2][B * H];                        // final hidden (fp32, classifier)
__device__ __nv_bfloat16 g_hB[2][B * H];               // hidden state (bf16, exchange)
constexpr int NGRP = 8, GRP = 16;                      // 8 row-groups x 16 dim CTAs
// Per-CTA publish flags, 128B apart -> zero write contention, parallel polls
__device__ unsigned g_flag[NGRP][GRP][32];

// ---------------------------------------------------------------------------
// Helpers
// ---------------------------------------------------------------------------
__device__ __forceinline__ void mma_bf16(float c[4], const uint32_t a[4], const uint32_t b[2]) {
    asm volatile(
        "mma.sync.aligned.m16n8k16.row.col.f32.bf16.bf16.f32 "
        "{%0,%1,%2,%3}, {%4,%5,%6,%7}, {%8,%9}, {%0,%1,%2,%3};\n"
        : "+f"(c[0]), "+f"(c[1]), "+f"(c[2]), "+f"(c[3])
        : "r"(a[0]), "r"(a[1]), "r"(a[2]), "r"(a[3]), "r"(b[0]), "r"(b[1]));
}

__device__ __forceinline__ void cp16(void* dst_smem, const void* src) {
    uint32_t d = (uint32_t)__cvta_generic_to_shared(dst_smem);
    asm volatile("cp.async.cg.shared.global [%0], [%1], 16;" :: "r"(d), "l"(src));
}
#define CP_COMMIT()  asm volatile("cp.async.commit_group;" ::: "memory")
#define CP_WAIT0()   asm volatile("cp.async.wait_group 0;" ::: "memory")

// ---------------------------------------------------------------------------
// Init (runs every launch — graph replays)
// ---------------------------------------------------------------------------
__global__ void init_kernel() {
    const int i = blockIdx.x * blockDim.x + threadIdx.x;
    if (i < 2 * B * H) {
        ((float*)g_h)[i] = 0.0f;
        ((__nv_bfloat16*)g_hB)[i] = __float2bfloat16(0.0f);
    }
    if (i < NGRP * GRP * 32) ((unsigned*)g_flag)[i] = 0u;
}

// ---------------------------------------------------------------------------
// Prep: transpose conv_w -> g_T
// ---------------------------------------------------------------------------
__global__ void prep_kernel(const float* __restrict__ conv_w) {
    const int idx = blockIdx.x * blockDim.x + threadIdx.x;
    if (idx < H * V * 3) {
        const int k = idx % 3;
        const int v = (idx / 3) % V;
        const int h = idx / (3 * V);
        g_T[k][v][h] = conv_w[idx];
    }
}

// ---------------------------------------------------------------------------
// Embedding "conv" -> bf16 y
// ---------------------------------------------------------------------------
__global__ void embed_kernel(const int* __restrict__ x, const float* __restrict__ conv_b) {
    const int n = blockIdx.x;      // n = t*B + b
    const int t = n >> 7;
    const int b = n & 127;
    const int x0 = x[b * L + t];
    const int xm = (t > 0) ? x[b * L + t - 1] : -1;
    const int xp = (t < L - 1) ? x[b * L + t + 1] : -1;
    const int hb = threadIdx.x * 4;

    float4 acc = *(const float4*)(conv_b + hb);
    {
        const float4 e = *(const float4*)(&g_T[1][x0][hb]);
        acc.x += e.x; acc.y += e.y; acc.z += e.z; acc.w += e.w;
    }
    if (xm >= 0) {
        const float4 e = *(const float4*)(&g_T[0][xm][hb]);
        acc.x += e.x; acc.y += e.y; acc.z += e.z; acc.w += e.w;
    }
    if (xp >= 0) {
        const float4 e = *(const float4*)(&g_T[2][xp][hb]);
        acc.x += e.x; acc.y += e.y; acc.z += e.z; acc.w += e.w;
    }
    __nv_bfloat162 p0, p1;
    p0.x = __float2bfloat16_rn(fmaxf(acc.x, 0.0f));
    p0.y = __float2bfloat16_rn(fmaxf(acc.y, 0.0f));
    p1.x = __float2bfloat16_rn(fmaxf(acc.z, 0.0f));
    p1.y = __float2bfloat16_rn(fmaxf(acc.w, 0.0f));
    *(__nv_bfloat162*)(g_yB + (size_t)n * H + hb) = p0;
    *(__nv_bfloat162*)(g_yB + (size_t)n * H + hb + 2) = p1;
}

// ---------------------------------------------------------------------------
// Fused persistent GRU kernel v15 = v14 + flag barrier + gi split.
// Warp (nt, kh): nt=warp>>1 owns cols nt*24..+23, kh=warp&1 owns K-half.
// Barrier: each CTA st.release's its OWN 128B-strided flag (no atomic
// contention); 16 spinner threads poll the 16 peer flags in parallel.
// Step: [top: wait y-cp + sync] [giA: 8 chunks, covers skew] [flag spin]
//       [sync] [cp h] [giB: 8 chunks, hides cp] [cp-wait + sync]
//       [gh mma (reg weights)] [sync] [Red 2 planes, single write] [sync]
//       [gates + h STG] [sync] [y(t+1) cp + flag release].
// ---------------------------------------------------------------------------
constexpr int WHH_OFF = 96 * 256;            // 24576 words
constexpr int YOFF = 2 * 96 * 256;           // 49152
constexpr int HOFF = YOFF + 4096;            // 53248
constexpr int GRU_SMEM = (HOFF + 4096) * 4;  // 229,376 B
constexpr int RLD = 164;                     // Red row stride (floats)
constexpr int RPLANE = 16 * RLD;             // per-kh plane (floats)
constexpr int NCACHE = 6;                    // w_ih reg-cached chunks

__global__ void __launch_bounds__(256, 1) gru_kernel(const float* __restrict__ w_ih,
                                                     const float* __restrict__ w_hh,
                                                     const float* __restrict__ b_ih,
                                                     const float* __restrict__ b_hh) {
    extern __shared__ uint32_t smw[];
    float* Red = (float*)(smw + YOFF);       // 2 planes aliased over y+h tiles

    const int tid = threadIdx.x, warp = tid >> 5, lane = tid & 31;
    const int g = lane >> 2, tig = lane & 3;
    const int nt = warp >> 1, kh = warp & 1;
    const int rg = blockIdx.x >> 4, dg = blockIdx.x & 15;
    const int pr = tid >> 4, ps = tid & 15;  // cp/sts row + 16-word segment

    // Prologue: y(0) via cp.async
    {
        const __nv_bfloat16* src = g_yB + (size_t)(rg * 16 + pr) * H + ps * 32;
#pragma unroll
        for (int i = 0; i < 4; i++) {
            const int w0 = ps * 16 + 4 * i;
            cp16(smw + YOFF + pr * 256 + (w0 ^ ((pr & 7) << 2)), src + i * 8);
        }
        CP_COMMIT();
    }

    // Weights -> SMEM bf16 with XOR swizzle
    for (int i = tid; i < 2 * 96 * 128; i += 256) {
        const int mat = i / (96 * 128);
        const int rem = i - mat * (96 * 128);
        const int n = rem >> 7, f4 = rem & 127;
        const int tt = n >> 3;
        const int grow = (tt % 3) * H + dg * 32 + (tt / 3) * 8 + (n & 7);
        const float* srcm = mat ? w_hh : w_ih;
        const float4 v = *(const float4*)(srcm + (size_t)grow * H + f4 * 4);
        __nv_bfloat162 q0, q1;
        q0.x = __float2bfloat16_rn(v.x); q0.y = __float2bfloat16_rn(v.y);
        q1.x = __float2bfloat16_rn(v.z); q1.y = __float2bfloat16_rn(v.w);
        const int w0 = (f4 * 2) ^ ((n & 7) << 2);
        uint2 pk;
        pk.x = *(const uint32_t*)&q0;
        pk.y = *(const uint32_t*)&q1;
        *(uint2*)(smw + mat * WHH_OFF + n * 256 + w0) = pk;
    }

    // Gate-phase setup: thread -> (row_e, dim pair j2)
    const int row_e = tid >> 4;
    const int j2 = (tid & 15) * 2;
    const int grow_e = rg * 16 + row_e;
    const int jg = dg * 32 + j2;
    float2 br2, bz2;
    {
        float2 a = *(const float2*)(b_ih + jg), b = *(const float2*)(b_hh + jg);
        br2 = make_float2(a.x + b.x, a.y + b.y);
        a = *(const float2*)(b_ih + H + jg); b = *(const float2*)(b_hh + H + jg);
        bz2 = make_float2(a.x + b.x, a.y + b.y);
    }
    const float2 bin2 = *(const float2*)(b_ih + 2 * H + jg);
    const float2 bhn2 = *(const float2*)(b_hh + 2 * H + jg);

    // Fragment bases
    const uint32_t* Yb0 = smw + YOFF + g * 256;
    const uint32_t* Yb1 = smw + YOFF + (g + 8) * 256;
    const uint32_t* Hb0 = smw + HOFF + g * 256;
    const uint32_t* Hb1 = smw + HOFF + (g + 8) * 256;
    const uint32_t* Wi0 = smw + (nt * 24 + g) * 256;
    const uint32_t* Wh0 = smw + WHH_OFF + (nt * 24 + g) * 256;
    const int xw = g << 2;
    const int kbase = kh * 128;

    __syncthreads();

    // w_hh b-fragments -> registers (all 16 chunks; reused 1024 steps)
    uint32_t breg[16][3][2];
#pragma unroll
    for (int ck = 0; ck < 16; ck++) {
        const int w = kbase + ck * 8 + tig;
        const int wx0 = w ^ xw;
        const int wx4 = (w + 4) ^ xw;
        breg[ck][0][0] = Wh0[wx0];            breg[ck][0][1] = Wh0[wx4];
        breg[ck][1][0] = Wh0[8 * 256 + wx0];  breg[ck][1][1] = Wh0[8 * 256 + wx4];
        breg[ck][2][0] = Wh0[16 * 256 + wx0]; breg[ck][2][1] = Wh0[16 * 256 + wx4];
    }
    // w_ih b-fragments for the first NCACHE chunks
    uint32_t bregI[NCACHE][3][2];
#pragma unroll
    for (int ck = 0; ck < NCACHE; ck++) {
        const int w = kbase + ck * 8 + tig;
        const int wx0 = w ^ xw;
        const int wx4 = (w + 4) ^ xw;
        bregI[ck][0][0] = Wi0[wx0];            bregI[ck][0][1] = Wi0[wx4];
        bregI[ck][1][0] = Wi0[8 * 256 + wx0];  bregI[ck][1][1] = Wi0[8 * 256 + wx4];
        bregI[ck][2][0] = Wi0[16 * 256 + wx0]; bregI[ck][2][1] = Wi0[16 * 256 + wx4];
    }

    float2 ho2 = make_float2(0.0f, 0.0f);   // h_old lives in registers
    int p = 0;
    for (int t = 0; t < L; t++) {
        const bool hasnext = (t + 1 < L);

        // ---- top: y(t) cp (committed at end of prev step / prologue) done ----
        CP_WAIT0();
        __syncthreads();

        // ---- giA: chunks 0..7 of y(t) x w_ih (covers residual peer skew) ----
        float c0[4] = {}, c1[4] = {}, c2i[4] = {}, c2h[4] = {};
#pragma unroll
        for (int ck = 0; ck < NCACHE; ck++) {
            const int w = kbase + ck * 8 + tig;
            const int wx0 = w ^ xw;
            const int wx4 = (w + 4) ^ xw;
            uint32_t ay[4];
            ay[0] = Yb0[wx0]; ay[1] = Yb1[wx0]; ay[2] = Yb0[wx4]; ay[3] = Yb1[wx4];
            mma_bf16(c0, ay, bregI[ck][0]);
            mma_bf16(c1, ay, bregI[ck][1]);
            mma_bf16(c2i, ay, bregI[ck][2]);
        }
#pragma unroll
        for (int ck = NCACHE; ck < 8; ck++) {
            const int w = kbase + ck * 8 + tig;
            const int wx0 = w ^ xw;
            const int wx4 = (w + 4) ^ xw;
            uint32_t ay[4], bb[2];
            ay[0] = Yb0[wx0]; ay[1] = Yb1[wx0]; ay[2] = Yb0[wx4]; ay[3] = Yb1[wx4];
            bb[0] = Wi0[wx0]; bb[1] = Wi0[wx4];
            mma_bf16(c0, ay, bb);
            bb[0] = Wi0[8 * 256 + wx0]; bb[1] = Wi0[8 * 256 + wx4];
            mma_bf16(c1, ay, bb);
            bb[0] = Wi0[16 * 256 + wx0]; bb[1] = Wi0[16 * 256 + wx4];
            mma_bf16(c2i, ay, bb);
        }

        // ---- wait: all 16 peer flags >= t (parallel, contention-free) ----
        if (tid < GRP) {
            unsigned v;
            do {
                asm volatile("ld.acquire.gpu.u32 %0, [%1];"
                             : "=r"(v) : "l"(&g_flag[rg][tid][0]) : "memory");
            } while (v < (unsigned)t);
        }
        __syncthreads();

        // ---- cp h(t) tile; latency hides under giB ----
        {
            const __nv_bfloat16* src = g_hB[p] + (size_t)(rg * 16 + pr) * H + ps * 32;
#pragma unroll
            for (int i = 0; i < 4; i++) {
                const int w0 = ps * 16 + 4 * i;
                cp16(smw + HOFF + pr * 256 + (w0 ^ ((pr & 7) << 2)), src + i * 8);
            }
            CP_COMMIT();
        }

        // ---- giB: chunks 8..15 of y(t) x w_ih ----
#pragma unroll 4
        for (int ck = 8; ck < 16; ck++) {
            const int w = kbase + ck * 8 + tig;
            const int wx0 = w ^ xw;
            const int wx4 = (w + 4) ^ xw;
            uint32_t ay[4], bb[2];
            ay[0] = Yb0[wx0]; ay[1] = Yb1[wx0]; ay[2] = Yb0[wx4]; ay[3] = Yb1[wx4];
            bb[0] = Wi0[wx0]; bb[1] = Wi0[wx4];
            mma_bf16(c0, ay, bb);
            bb[0] = Wi0[8 * 256 + wx0]; bb[1] = Wi0[8 * 256 + wx4];
            mma_bf16(c1, ay, bb);
            bb[0] = Wi0[16 * 256 + wx0]; bb[1] = Wi0[16 * 256 + wx4];
            mma_bf16(c2i, ay, bb);
        }

        CP_WAIT0();
        __syncthreads();   // h tile complete + all gi y-tile reads done

        // ---- gh mma: h(t) x w_hh (weights from registers) ----
#pragma unroll
        for (int ck = 0; ck < 16; ck++) {
            const int w = kbase + ck * 8 + tig;
            const int wx0 = w ^ xw;
            const int wx4 = (w + 4) ^ xw;
            uint32_t ah[4];
            ah[0] = Hb0[wx0]; ah[1] = Hb1[wx0]; ah[2] = Hb0[wx4]; ah[3] = Hb1[wx4];
            mma_bf16(c0, ah, breg[ck][0]);
            mma_bf16(c1, ah, breg[ck][1]);
            mma_bf16(c2h, ah, breg[ck][2]);
        }
        __syncthreads();   // y+h tile reads done -> Red planes may overwrite

        // ---- single Red write pass: each kh warp writes its own plane ----
        {
            float* Ra = Red + kh * RPLANE + g * RLD;
            float* Rb = Red + kh * RPLANE + (g + 8) * RLD;
            const int n0 = nt * 24 + 2 * tig;
            const int nd = nt * 8 + 2 * tig;
            *(float2*)&Ra[n0] = make_float2(c0[0], c0[1]);
            *(float2*)&Rb[n0] = make_float2(c0[2], c0[3]);
            *(float2*)&Ra[n0 + 8] = make_float2(c1[0], c1[1]);
            *(float2*)&Rb[n0 + 8] = make_float2(c1[2], c1[3]);
            *(float2*)&Ra[96 + nd] = make_float2(c2i[0], c2i[1]);
            *(float2*)&Rb[96 + nd] = make_float2(c2i[2], c2i[3]);
            *(float2*)&Ra[128 + nd] = make_float2(c2h[0], c2h[1]);
            *(float2*)&Rb[128 + nd] = make_float2(c2h[2], c2h[3]);
        }
        __syncthreads();

        // ---- gates: sum the two kh planes; h_old from registers ----
        {
            const float* R0 = Red + row_e * RLD;
            const float* R1 = Red + RPLANE + row_e * RLD;
            const int rcol = (j2 >> 3) * 24 + (j2 & 7);
            const float2 rpa = *(const float2*)&R0[rcol],      rpb = *(const float2*)&R1[rcol];
            const float2 zpa = *(const float2*)&R0[rcol + 8],  zpb = *(const float2*)&R1[rcol + 8];
            const float2 nia = *(const float2*)&R0[96 + j2],   nib = *(const float2*)&R1[96 + j2];
            const float2 nha = *(const float2*)&R0[128 + j2],  nhb = *(const float2*)&R1[128 + j2];
            const float r0 = 1.0f / (1.0f + __expf(-(rpa.x + rpb.x + br2.x)));
            const float r1 = 1.0f / (1.0f + __expf(-(rpa.y + rpb.y + br2.y)));
            const float z0 = 1.0f / (1.0f + __expf(-(zpa.x + zpb.x + bz2.x)));
            const float z1 = 1.0f / (1.0f + __expf(-(zpa.y + zpb.y + bz2.y)));
            const float n0v = tanhf(nia.x + nib.x + bin2.x + r0 * (nha.x + nhb.x + bhn2.x));
            const float n1v = tanhf(nia.y + nib.y + bin2.y + r1 * (nha.y + nhb.y + bhn2.y));
            float2 hn;
            hn.x = (1.0f - z0) * n0v + z0 * ho2.x;
            hn.y = (1.0f - z1) * n1v + z1 * ho2.y;
            ho2 = hn;
            __nv_bfloat162 hb;
            hb.x = __float2bfloat16_rn(hn.x);
            hb.y = __float2bfloat16_rn(hn.y);
            *(__nv_bfloat162*)(g_hB[p ^ 1] + (size_t)grow_e * H + jg) = hb;
            if (t == L - 1) *(float2*)(g_h[0] + (size_t)grow_e * H + jg) = hn;
        }

        __syncthreads();   // Red reads + h STG done

        // ---- y(t+1) cp into y tile (overlaps release + next spin) ----
        if (hasnext) {
            const __nv_bfloat16* src = g_yB + (size_t)((t + 1) * B + rg * 16 + pr) * H + ps * 32;
#pragma unroll
            for (int i = 0; i < 4; i++) {
                const int w0 = ps * 16 + 4 * i;
                cp16(smw + YOFF + pr * 256 + (w0 ^ ((pr & 7) << 2)), src + i * 8);
            }
        }
        CP_COMMIT();

        // ---- release: publish h(t+1) on this CTA's own flag ----
        if (tid == 0) {
            const unsigned tgt = (unsigned)(t + 1);
            asm volatile("st.release.gpu.global.u32 [%0], %1;"
                         :: "l"(&g_flag[rg][dg][0]), "r"(tgt) : "memory");
        }
        p ^= 1;
    }
}

// ---------------------------------------------------------------------------
// Classifier
// ---------------------------------------------------------------------------
__global__ void classifier_kernel(const float* __restrict__ cls_w,
                                  const float* __restrict__ cls_b,
                                  float* __restrict__ out) {
    const int b = blockIdx.x / C;
    const int cc = blockIdx.x % C;
    const float* h = g_h[0] + b * H;
    const float* w = cls_w + cc * H;
    float s = 0.0f;
    for (int k = threadIdx.x; k < H; k += 64) s += h[k] * w[k];
#pragma unroll
    for (int o = 16; o > 0; o >>= 1) s += __shfl_down_sync(0xffffffffu, s, o);
    __shared__ float red[2];
    if ((threadIdx.x & 31) == 0) red[threadIdx.x >> 5] = s;
    __syncthreads();
    if (threadIdx.x == 0) out[b * C + cc] = red[0] + red[1] + cls_b[cc];
}

// ---------------------------------------------------------------------------
// Launch
// ---------------------------------------------------------------------------
extern "C" void kernel_launch(void* const* d_in, const int* in_sizes, int n_in,
                              void* d_out, int out_size) {
    const int*   x      = (const int*)d_in[0];
    const float* conv_w = (const float*)d_in[1];
    const float* conv_b = (const float*)d_in[2];
    const float* w_ih   = (const float*)d_in[3];
    const float* w_hh   = (const float*)d_in[4];
    const float* b_ih   = (const float*)d_in[5];
    const float* b_hh   = (const float*)d_in[6];
    const float* cls_w  = (const float*)d_in[7];
    const float* cls_b  = (const float*)d_in[8];
    float* out = (float*)d_out;

    cudaFuncSetAttribute(gru_kernel, cudaFuncAttributeMaxDynamicSharedMemorySize, GRU_SMEM);

    init_kernel<<<512, 256>>>();
    prep_kernel<<<(H * V * 3 + 255) / 256, 256>>>(conv_w);
    embed_kernel<<<NROW, 128>>>(x, conv_b);
    gru_kernel<<<NGRP * GRP, 256, GRU_SMEM>>>(w_ih, w_hh, b_ih, b_hh);
    classifier_kernel<<<B * C, 64>>>(cls_w, cls_b, out);
}

// round 16
// speedup vs baseline: 1.2949x; 1.0350x over previous
#include <cuda_runtime.h>
#include <cuda_bf16.h>
#include <cstdint>

// Problem constants
constexpr int B = 128, L = 1024, V = 512, H = 512, C = 20;
constexpr int NROW = L * B;        // 131072

// ---------------------------------------------------------------------------
// Device scratch
// ---------------------------------------------------------------------------
__device__ float g_T[3][V][H];                         // transposed conv weights
__device__ __nv_bfloat16 g_yB[(size_t)NROW * H];       // conv output (bf16)
__device__ float g_h[2][B * H];                        // final hidden (fp32, classifier)
__device__ __nv_bfloat16 g_hB[2][B * H];               // hidden state (bf16, exchange)
constexpr int NGRP = 8, GRP = 16;                      // 8 row-groups x 16 dim CTAs
// Per-CTA publish flags, 128B apart -> zero write contention, parallel polls
__device__ unsigned g_flag[NGRP][GRP][32];

// ---------------------------------------------------------------------------
// Helpers
// ---------------------------------------------------------------------------
__device__ __forceinline__ void mma_bf16(float c[4], const uint32_t a[4], const uint32_t b[2]) {
    asm volatile(
        "mma.sync.aligned.m16n8k16.row.col.f32.bf16.bf16.f32 "
        "{%0,%1,%2,%3}, {%4,%5,%6,%7}, {%8,%9}, {%0,%1,%2,%3};\n"
        : "+f"(c[0]), "+f"(c[1]), "+f"(c[2]), "+f"(c[3])
        : "r"(a[0]), "r"(a[1]), "r"(a[2]), "r"(a[3]), "r"(b[0]), "r"(b[1]));
}

__device__ __forceinline__ void cp16(void* dst_smem, const void* src) {
    uint32_t d = (uint32_t)__cvta_generic_to_shared(dst_smem);
    asm volatile("cp.async.cg.shared.global [%0], [%1], 16;" :: "r"(d), "l"(src));
}
#define CP_COMMIT()  asm volatile("cp.async.commit_group;" ::: "memory")
#define CP_WAIT0()   asm volatile("cp.async.wait_group 0;" ::: "memory")

// ---------------------------------------------------------------------------
// Init (runs every launch — graph replays)
// ---------------------------------------------------------------------------
__global__ void init_kernel() {
    const int i = blockIdx.x * blockDim.x + threadIdx.x;
    if (i < 2 * B * H) {
        ((float*)g_h)[i] = 0.0f;
        ((__nv_bfloat16*)g_hB)[i] = __float2bfloat16(0.0f);
    }
    if (i < NGRP * GRP * 32) ((unsigned*)g_flag)[i] = 0u;
}

// ---------------------------------------------------------------------------
// Prep: transpose conv_w -> g_T
// ---------------------------------------------------------------------------
__global__ void prep_kernel(const float* __restrict__ conv_w) {
    const int idx = blockIdx.x * blockDim.x + threadIdx.x;
    if (idx < H * V * 3) {
        const int k = idx % 3;
        const int v = (idx / 3) % V;
        const int h = idx / (3 * V);
        g_T[k][v][h] = conv_w[idx];
    }
}

// ---------------------------------------------------------------------------
// Embedding "conv" -> bf16 y
// ---------------------------------------------------------------------------
__global__ void embed_kernel(const int* __restrict__ x, const float* __restrict__ conv_b) {
    const int n = blockIdx.x;      // n = t*B + b
    const int t = n >> 7;
    const int b = n & 127;
    const int x0 = x[b * L + t];
    const int xm = (t > 0) ? x[b * L + t - 1] : -1;
    const int xp = (t < L - 1) ? x[b * L + t + 1] : -1;
    const int hb = threadIdx.x * 4;

    float4 acc = *(const float4*)(conv_b + hb);
    {
        const float4 e = *(const float4*)(&g_T[1][x0][hb]);
        acc.x += e.x; acc.y += e.y; acc.z += e.z; acc.w += e.w;
    }
    if (xm >= 0) {
        const float4 e = *(const float4*)(&g_T[0][xm][hb]);
        acc.x += e.x; acc.y += e.y; acc.z += e.z; acc.w += e.w;
    }
    if (xp >= 0) {
        const float4 e = *(const float4*)(&g_T[2][xp][hb]);
        acc.x += e.x; acc.y += e.y; acc.z += e.z; acc.w += e.w;
    }
    __nv_bfloat162 p0, p1;
    p0.x = __float2bfloat16_rn(fmaxf(acc.x, 0.0f));
    p0.y = __float2bfloat16_rn(fmaxf(acc.y, 0.0f));
    p1.x = __float2bfloat16_rn(fmaxf(acc.z, 0.0f));
    p1.y = __float2bfloat16_rn(fmaxf(acc.w, 0.0f));
    *(__nv_bfloat162*)(g_yB + (size_t)n * H + hb) = p0;
    *(__nv_bfloat162*)(g_yB + (size_t)n * H + hb + 2) = p1;
}

// ---------------------------------------------------------------------------
// Fused persistent GRU kernel v16 = v15 + (w_hh dropped from SMEM: breg
// loaded straight from global; dedicated Red region in the freed space;
// y(t+1) cp moved right after the h cp-wait; post-gh sync deleted).
// SMEM: [0, 24576w) w_ih; [YOFF, +4096w) y tile; [HOFF, +4096w) h tile;
//       [REDOFF, +2*RPLANE) Red (dedicated).
// Step: [top: wait y-cp + sync] [giA] [flag spin + sync] [cp h] [giB]
//       [cp-wait + sync] [y(t+1) cp] [gh mma] [Red write] [sync]
//       [gates + h STG] [sync] [flag release].          (5 syncs)
// ---------------------------------------------------------------------------
constexpr int YOFF = 96 * 256;               // 24576 words
constexpr int HOFF = YOFF + 4096;            // 28672
constexpr int REDOFF = HOFF + 4096;          // 32768 (words)
constexpr int RLD = 164;                     // Red row stride (floats)
constexpr int RPLANE = 16 * RLD;             // per-kh plane (floats)
constexpr int GRU_SMEM = (REDOFF + 2 * RPLANE) * 4;   // 152,064 B
constexpr int NCACHE = 6;                    // w_ih reg-cached chunks

__global__ void __launch_bounds__(256, 1) gru_kernel(const float* __restrict__ w_ih,
                                                     const float* __restrict__ w_hh,
                                                     const float* __restrict__ b_ih,
                                                     const float* __restrict__ b_hh) {
    extern __shared__ uint32_t smw[];
    float* Red = (float*)(smw + REDOFF);     // dedicated (no aliasing)

    const int tid = threadIdx.x, warp = tid >> 5, lane = tid & 31;
    const int g = lane >> 2, tig = lane & 3;
    const int nt = warp >> 1, kh = warp & 1;
    const int rg = blockIdx.x >> 4, dg = blockIdx.x & 15;
    const int pr = tid >> 4, ps = tid & 15;  // cp/sts row + 16-word segment

    // Prologue: y(0) via cp.async
    {
        const __nv_bfloat16* src = g_yB + (size_t)(rg * 16 + pr) * H + ps * 32;
#pragma unroll
        for (int i = 0; i < 4; i++) {
            const int w0 = ps * 16 + 4 * i;
            cp16(smw + YOFF + pr * 256 + (w0 ^ ((pr & 7) << 2)), src + i * 8);
        }
        CP_COMMIT();
    }

    // w_ih -> SMEM bf16 with XOR swizzle (w_hh no longer stored in SMEM)
    for (int i = tid; i < 96 * 128; i += 256) {
        const int n = i >> 7, f4 = i & 127;
        const int tt = n >> 3;
        const int grow = (tt % 3) * H + dg * 32 + (tt / 3) * 8 + (n & 7);
        const float4 v = *(const float4*)(w_ih + (size_t)grow * H + f4 * 4);
        __nv_bfloat162 q0, q1;
        q0.x = __float2bfloat16_rn(v.x); q0.y = __float2bfloat16_rn(v.y);
        q1.x = __float2bfloat16_rn(v.z); q1.y = __float2bfloat16_rn(v.w);
        const int w0 = (f4 * 2) ^ ((n & 7) << 2);
        uint2 pk;
        pk.x = *(const uint32_t*)&q0;
        pk.y = *(const uint32_t*)&q1;
        *(uint2*)(smw + n * 256 + w0) = pk;
    }

    // Gate-phase setup: thread -> (row_e, dim pair j2)
    const int row_e = tid >> 4;
    const int j2 = (tid & 15) * 2;
    const int grow_e = rg * 16 + row_e;
    const int jg = dg * 32 + j2;
    float2 br2, bz2;
    {
        float2 a = *(const float2*)(b_ih + jg), b = *(const float2*)(b_hh + jg);
        br2 = make_float2(a.x + b.x, a.y + b.y);
        a = *(const float2*)(b_ih + H + jg); b = *(const float2*)(b_hh + H + jg);
        bz2 = make_float2(a.x + b.x, a.y + b.y);
    }
    const float2 bin2 = *(const float2*)(b_ih + 2 * H + jg);
    const float2 bhn2 = *(const float2*)(b_hh + 2 * H + jg);

    // Fragment bases
    const uint32_t* Yb0 = smw + YOFF + g * 256;
    const uint32_t* Yb1 = smw + YOFF + (g + 8) * 256;
    const uint32_t* Hb0 = smw + HOFF + g * 256;
    const uint32_t* Hb1 = smw + HOFF + (g + 8) * 256;
    const uint32_t* Wi0 = smw + (nt * 24 + g) * 256;
    const int xw = g << 2;
    const int kbase = kh * 128;

    // w_hh b-fragments -> registers, loaded DIRECTLY from global.
    // breg[ck][nb][q]: bf16 pair (k, k+1), k = 2*(kbase + ck*8 + tig + q*4),
    // of w_hh row  nb*H + dg*32 + nt*8 + g.
    uint32_t breg[16][3][2];
#pragma unroll
    for (int nb = 0; nb < 3; nb++) {
        const float* wrow = w_hh + (size_t)(nb * H + dg * 32 + nt * 8 + g) * H;
#pragma unroll
        for (int ck = 0; ck < 16; ck++) {
#pragma unroll
            for (int q = 0; q < 2; q++) {
                const int k0 = 2 * (kbase + ck * 8 + tig + q * 4);
                __nv_bfloat162 pk;
                pk.x = __float2bfloat16_rn(wrow[k0]);
                pk.y = __float2bfloat16_rn(wrow[k0 + 1]);
                breg[ck][nb][q] = *(const uint32_t*)&pk;
            }
        }
    }

    __syncthreads();   // w_ih tile ready

    // w_ih b-fragments for the first NCACHE chunks (from SMEM)
    uint32_t bregI[NCACHE][3][2];
#pragma unroll
    for (int ck = 0; ck < NCACHE; ck++) {
        const int w = kbase + ck * 8 + tig;
        const int wx0 = w ^ xw;
        const int wx4 = (w + 4) ^ xw;
        bregI[ck][0][0] = Wi0[wx0];            bregI[ck][0][1] = Wi0[wx4];
        bregI[ck][1][0] = Wi0[8 * 256 + wx0];  bregI[ck][1][1] = Wi0[8 * 256 + wx4];
        bregI[ck][2][0] = Wi0[16 * 256 + wx0]; bregI[ck][2][1] = Wi0[16 * 256 + wx4];
    }

    float2 ho2 = make_float2(0.0f, 0.0f);   // h_old lives in registers
    int p = 0;
    for (int t = 0; t < L; t++) {
        const bool hasnext = (t + 1 < L);

        // ---- top: y(t) cp done (issued mid-previous-step -> long overlap) ----
        CP_WAIT0();
        __syncthreads();

        // ---- giA: chunks 0..7 of y(t) x w_ih (covers residual peer skew) ----
        float c0[4] = {}, c1[4] = {}, c2i[4] = {}, c2h[4] = {};
#pragma unroll
        for (int ck = 0; ck < NCACHE; ck++) {
            const int w = kbase + ck * 8 + tig;
            const int wx0 = w ^ xw;
            const int wx4 = (w + 4) ^ xw;
            uint32_t ay[4];
            ay[0] = Yb0[wx0]; ay[1] = Yb1[wx0]; ay[2] = Yb0[wx4]; ay[3] = Yb1[wx4];
            mma_bf16(c0, ay, bregI[ck][0]);
            mma_bf16(c1, ay, bregI[ck][1]);
            mma_bf16(c2i, ay, bregI[ck][2]);
        }
#pragma unroll
        for (int ck = NCACHE; ck < 8; ck++) {
            const int w = kbase + ck * 8 + tig;
            const int wx0 = w ^ xw;
            const int wx4 = (w + 4) ^ xw;
            uint32_t ay[4], bb[2];
            ay[0] = Yb0[wx0]; ay[1] = Yb1[wx0]; ay[2] = Yb0[wx4]; ay[3] = Yb1[wx4];
            bb[0] = Wi0[wx0]; bb[1] = Wi0[wx4];
            mma_bf16(c0, ay, bb);
            bb[0] = Wi0[8 * 256 + wx0]; bb[1] = Wi0[8 * 256 + wx4];
            mma_bf16(c1, ay, bb);
            bb[0] = Wi0[16 * 256 + wx0]; bb[1] = Wi0[16 * 256 + wx4];
            mma_bf16(c2i, ay, bb);
        }

        // ---- wait: all 16 peer flags >= t (parallel, contention-free) ----
        if (tid < GRP) {
            unsigned v;
            do {
                asm volatile("ld.acquire.gpu.u32 %0, [%1];"
                             : "=r"(v) : "l"(&g_flag[rg][tid][0]) : "memory");
            } while (v < (unsigned)t);
        }
        __syncthreads();

        // ---- cp h(t) tile; latency hides under giB ----
        {
            const __nv_bfloat16* src = g_hB[p] + (size_t)(rg * 16 + pr) * H + ps * 32;
#pragma unroll
            for (int i = 0; i < 4; i++) {
                const int w0 = ps * 16 + 4 * i;
                cp16(smw + HOFF + pr * 256 + (w0 ^ ((pr & 7) << 2)), src + i * 8);
            }
            CP_COMMIT();
        }

        // ---- giB: chunks 8..15 of y(t) x w_ih ----
#pragma unroll 4
        for (int ck = 8; ck < 16; ck++) {
            const int w = kbase + ck * 8 + tig;
            const int wx0 = w ^ xw;
            const int wx4 = (w + 4) ^ xw;
            uint32_t ay[4], bb[2];
            ay[0] = Yb0[wx0]; ay[1] = Yb1[wx0]; ay[2] = Yb0[wx4]; ay[3] = Yb1[wx4];
            bb[0] = Wi0[wx0]; bb[1] = Wi0[wx4];
            mma_bf16(c0, ay, bb);
            bb[0] = Wi0[8 * 256 + wx0]; bb[1] = Wi0[8 * 256 + wx4];
            mma_bf16(c1, ay, bb);
            bb[0] = Wi0[16 * 256 + wx0]; bb[1] = Wi0[16 * 256 + wx4];
            mma_bf16(c2i, ay, bb);
        }

        CP_WAIT0();
        __syncthreads();   // h tile complete + all gi y-tile reads done

        // ---- y(t+1) cp into y tile NOW: overlaps gh + Red + gates + release ----
        if (hasnext) {
            const __nv_bfloat16* src = g_yB + (size_t)((t + 1) * B + rg * 16 + pr) * H + ps * 32;
#pragma unroll
            for (int i = 0; i < 4; i++) {
                const int w0 = ps * 16 + 4 * i;
                cp16(smw + YOFF + pr * 256 + (w0 ^ ((pr & 7) << 2)), src + i * 8);
            }
        }
        CP_COMMIT();

        // ---- gh mma: h(t) x w_hh (weights from registers) ----
#pragma unroll
        for (int ck = 0; ck < 16; ck++) {
            const int w = kbase + ck * 8 + tig;
            const int wx0 = w ^ xw;
            const int wx4 = (w + 4) ^ xw;
            uint32_t ah[4];
            ah[0] = Hb0[wx0]; ah[1] = Hb1[wx0]; ah[2] = Hb0[wx4]; ah[3] = Hb1[wx4];
            mma_bf16(c0, ah, breg[ck][0]);
            mma_bf16(c1, ah, breg[ck][1]);
            mma_bf16(c2h, ah, breg[ck][2]);
        }

        // ---- Red write (dedicated region; warp-local, no pre-sync needed) ----
        {
            float* Ra = Red + kh * RPLANE + g * RLD;
            float* Rb = Red + kh * RPLANE + (g + 8) * RLD;
            const int n0 = nt * 24 + 2 * tig;
            const int nd = nt * 8 + 2 * tig;
            *(float2*)&Ra[n0] = make_float2(c0[0], c0[1]);
            *(float2*)&Rb[n0] = make_float2(c0[2], c0[3]);
            *(float2*)&Ra[n0 + 8] = make_float2(c1[0], c1[1]);
            *(float2*)&Rb[n0 + 8] = make_float2(c1[2], c1[3]);
            *(float2*)&Ra[96 + nd] = make_float2(c2i[0], c2i[1]);
            *(float2*)&Rb[96 + nd] = make_float2(c2i[2], c2i[3]);
            *(float2*)&Ra[128 + nd] = make_float2(c2h[0], c2h[1]);
            *(float2*)&Rb[128 + nd] = make_float2(c2h[2], c2h[3]);
        }
        __syncthreads();

        // ---- gates: sum the two kh planes; h_old from registers ----
        {
            const float* R0 = Red + row_e * RLD;
            const float* R1 = Red + RPLANE + row_e * RLD;
            const int rcol = (j2 >> 3) * 24 + (j2 & 7);
            const float2 rpa = *(const float2*)&R0[rcol],      rpb = *(const float2*)&R1[rcol];
            const float2 zpa = *(const float2*)&R0[rcol + 8],  zpb = *(const float2*)&R1[rcol + 8];
            const float2 nia = *(const float2*)&R0[96 + j2],   nib = *(const float2*)&R1[96 + j2];
            const float2 nha = *(const float2*)&R0[128 + j2],  nhb = *(const float2*)&R1[128 + j2];
            const float r0 = 1.0f / (1.0f + __expf(-(rpa.x + rpb.x + br2.x)));
            const float r1 = 1.0f / (1.0f + __expf(-(rpa.y + rpb.y + br2.y)));
            const float z0 = 1.0f / (1.0f + __expf(-(zpa.x + zpb.x + bz2.x)));
            const float z1 = 1.0f / (1.0f + __expf(-(zpa.y + zpb.y + bz2.y)));
            const float n0v = tanhf(nia.x + nib.x + bin2.x + r0 * (nha.x + nhb.x + bhn2.x));
            const float n1v = tanhf(nia.y + nib.y + bin2.y + r1 * (nha.y + nhb.y + bhn2.y));
            float2 hn;
            hn.x = (1.0f - z0) * n0v + z0 * ho2.x;
            hn.y = (1.0f - z1) * n1v + z1 * ho2.y;
            ho2 = hn;
            __nv_bfloat162 hb;
            hb.x = __float2bfloat16_rn(hn.x);
            hb.y = __float2bfloat16_rn(hn.y);
            *(__nv_bfloat162*)(g_hB[p ^ 1] + (size_t)grow_e * H + jg) = hb;
            if (t == L - 1) *(float2*)(g_h[0] + (size_t)grow_e * H + jg) = hn;
        }

        __syncthreads();   // h STG + Red reads done

        // ---- release: publish h(t+1) on this CTA's own flag ----
        if (tid == 0) {
            const unsigned tgt = (unsigned)(t + 1);
            asm volatile("st.release.gpu.global.u32 [%0], %1;"
                         :: "l"(&g_flag[rg][dg][0]), "r"(tgt) : "memory");
        }
        p ^= 1;
    }
}

// ---------------------------------------------------------------------------
// Classifier
// ---------------------------------------------------------------------------
__global__ void classifier_kernel(const float* __restrict__ cls_w,
                                  const float* __restrict__ cls_b,
                                  float* __restrict__ out) {
    const int b = blockIdx.x / C;
    const int cc = blockIdx.x % C;
    const float* h = g_h[0] + b * H;
    const float* w = cls_w + cc * H;
    float s = 0.0f;
    for (int k = threadIdx.x; k < H; k += 64) s += h[k] * w[k];
#pragma unroll
    for (int o = 16; o > 0; o >>= 1) s += __shfl_down_sync(0xffffffffu, s, o);
    __shared__ float red[2];
    if ((threadIdx.x & 31) == 0) red[threadIdx.x >> 5] = s;
    __syncthreads();
    if (threadIdx.x == 0) out[b * C + cc] = red[0] + red[1] + cls_b[cc];
}

// ---------------------------------------------------------------------------
// Launch
// ---------------------------------------------------------------------------
extern "C" void kernel_launch(void* const* d_in, const int* in_sizes, int n_in,
                              void* d_out, int out_size) {
    const int*   x      = (const int*)d_in[0];
    const float* conv_w = (const float*)d_in[1];
    const float* conv_b = (const float*)d_in[2];
    const float* w_ih   = (const float*)d_in[3];
    const float* w_hh   = (const float*)d_in[4];
    const float* b_ih   = (const float*)d_in[5];
    const float* b_hh   = (const float*)d_in[6];
    const float* cls_w  = (const float*)d_in[7];
    const float* cls_b  = (const float*)d_in[8];
    float* out = (float*)d_out;

    cudaFuncSetAttribute(gru_kernel, cudaFuncAttributeMaxDynamicSharedMemorySize, GRU_SMEM);

    init_kernel<<<512, 256>>>();
    prep_kernel<<<(H * V * 3 + 255) / 256, 256>>>(conv_w);
    embed_kernel<<<NROW, 128>>>(x, conv_b);
    gru_kernel<<<NGRP * GRP, 256, GRU_SMEM>>>(w_ih, w_hh, b_ih, b_hh);
    classifier_kernel<<<B * C, 64>>>(cls_w, cls_b, out);
}

// round 17
// speedup vs baseline: 1.4166x; 1.0940x over previous
#include <cuda_runtime.h>
#include <cuda_bf16.h>
#include <cstdint>

// Problem constants
constexpr int B = 128, L = 1024, V = 512, H = 512, C = 20;
constexpr int NROW = L * B;        // 131072

// ---------------------------------------------------------------------------
// Device scratch
// ---------------------------------------------------------------------------
__device__ float g_T[3][V][H];                         // transposed conv weights
__device__ __nv_bfloat16 g_yB[(size_t)NROW * H];       // conv output (bf16)
__device__ float g_h[2][B * H];                        // final hidden (fp32, classifier)
__device__ __nv_bfloat16 g_hB[2][B * H];               // hidden state (bf16, exchange)
constexpr int NGRP = 8, GRP = 16;                      // 8 row-groups x 16 dim CTAs
// Per-CTA publish flags, 128B apart -> zero write contention, parallel polls
__device__ unsigned g_flag[NGRP][GRP][32];

// ---------------------------------------------------------------------------
// Helpers
// ---------------------------------------------------------------------------
__device__ __forceinline__ void mma_bf16(float c[4], const uint32_t a[4], const uint32_t b[2]) {
    asm volatile(
        "mma.sync.aligned.m16n8k16.row.col.f32.bf16.bf16.f32 "
        "{%0,%1,%2,%3}, {%4,%5,%6,%7}, {%8,%9}, {%0,%1,%2,%3};\n"
        : "+f"(c[0]), "+f"(c[1]), "+f"(c[2]), "+f"(c[3])
        : "r"(a[0]), "r"(a[1]), "r"(a[2]), "r"(a[3]), "r"(b[0]), "r"(b[1]));
}

__device__ __forceinline__ void cp16(void* dst_smem, const void* src) {
    uint32_t d = (uint32_t)__cvta_generic_to_shared(dst_smem);
    asm volatile("cp.async.cg.shared.global [%0], [%1], 16;" :: "r"(d), "l"(src));
}
#define CP_COMMIT()  asm volatile("cp.async.commit_group;" ::: "memory")
#define CP_WAIT0()   asm volatile("cp.async.wait_group 0;" ::: "memory")

__device__ __forceinline__ float fast_sigmoid(float x) {
    return __fdividef(1.0f, 1.0f + __expf(-x));
}
__device__ __forceinline__ float fast_tanh(float x) {
    float r;
    asm("tanh.approx.f32 %0, %1;" : "=f"(r) : "f"(x));
    return r;
}

// ---------------------------------------------------------------------------
// Init (runs every launch — graph replays)
// ---------------------------------------------------------------------------
__global__ void init_kernel() {
    const int i = blockIdx.x * blockDim.x + threadIdx.x;
    if (i < 2 * B * H) {
        ((float*)g_h)[i] = 0.0f;
        ((__nv_bfloat16*)g_hB)[i] = __float2bfloat16(0.0f);
    }
    if (i < NGRP * GRP * 32) ((unsigned*)g_flag)[i] = 0u;
}

// ---------------------------------------------------------------------------
// Prep: transpose conv_w -> g_T
// ---------------------------------------------------------------------------
__global__ void prep_kernel(const float* __restrict__ conv_w) {
    const int idx = blockIdx.x * blockDim.x + threadIdx.x;
    if (idx < H * V * 3) {
        const int k = idx % 3;
        const int v = (idx / 3) % V;
        const int h = idx / (3 * V);
        g_T[k][v][h] = conv_w[idx];
    }
}

// ---------------------------------------------------------------------------
// Embedding "conv" -> bf16 y
// ---------------------------------------------------------------------------
__global__ void embed_kernel(const int* __restrict__ x, const float* __restrict__ conv_b) {
    const int n = blockIdx.x;      // n = t*B + b
    const int t = n >> 7;
    const int b = n & 127;
    const int x0 = x[b * L + t];
    const int xm = (t > 0) ? x[b * L + t - 1] : -1;
    const int xp = (t < L - 1) ? x[b * L + t + 1] : -1;
    const int hb = threadIdx.x * 4;

    float4 acc = *(const float4*)(conv_b + hb);
    {
        const float4 e = *(const float4*)(&g_T[1][x0][hb]);
        acc.x += e.x; acc.y += e.y; acc.z += e.z; acc.w += e.w;
    }
    if (xm >= 0) {
        const float4 e = *(const float4*)(&g_T[0][xm][hb]);
        acc.x += e.x; acc.y += e.y; acc.z += e.z; acc.w += e.w;
    }
    if (xp >= 0) {
        const float4 e = *(const float4*)(&g_T[2][xp][hb]);
        acc.x += e.x; acc.y += e.y; acc.z += e.z; acc.w += e.w;
    }
    __nv_bfloat162 p0, p1;
    p0.x = __float2bfloat16_rn(fmaxf(acc.x, 0.0f));
    p0.y = __float2bfloat16_rn(fmaxf(acc.y, 0.0f));
    p1.x = __float2bfloat16_rn(fmaxf(acc.z, 0.0f));
    p1.y = __float2bfloat16_rn(fmaxf(acc.w, 0.0f));
    *(__nv_bfloat162*)(g_yB + (size_t)n * H + hb) = p0;
    *(__nv_bfloat162*)(g_yB + (size_t)n * H + hb + 2) = p1;
}

// ---------------------------------------------------------------------------
// Fused persistent GRU kernel v17 = v16 + fast-math gates
// (sigmoid via EX2+RCP approx, tanh via tanh.approx.f32).
// SMEM: [0, 24576w) w_ih; [YOFF, +4096w) y tile; [HOFF, +4096w) h tile;
//       [REDOFF, +2*RPLANE) Red (dedicated).
// Step: [top: wait y-cp + sync] [giA] [flag spin + sync] [cp h] [giB]
//       [cp-wait + sync] [y(t+1) cp] [gh mma] [Red write] [sync]
//       [gates + h STG] [sync] [flag release].          (5 syncs)
// ---------------------------------------------------------------------------
constexpr int YOFF = 96 * 256;               // 24576 words
constexpr int HOFF = YOFF + 4096;            // 28672
constexpr int REDOFF = HOFF + 4096;          // 32768 (words)
constexpr int RLD = 164;                     // Red row stride (floats)
constexpr int RPLANE = 16 * RLD;             // per-kh plane (floats)
constexpr int GRU_SMEM = (REDOFF + 2 * RPLANE) * 4;   // 152,064 B
constexpr int NCACHE = 6;                    // w_ih reg-cached chunks

__global__ void __launch_bounds__(256, 1) gru_kernel(const float* __restrict__ w_ih,
                                                     const float* __restrict__ w_hh,
                                                     const float* __restrict__ b_ih,
                                                     const float* __restrict__ b_hh) {
    extern __shared__ uint32_t smw[];
    float* Red = (float*)(smw + REDOFF);     // dedicated (no aliasing)

    const int tid = threadIdx.x, warp = tid >> 5, lane = tid & 31;
    const int g = lane >> 2, tig = lane & 3;
    const int nt = warp >> 1, kh = warp & 1;
    const int rg = blockIdx.x >> 4, dg = blockIdx.x & 15;
    const int pr = tid >> 4, ps = tid & 15;  // cp/sts row + 16-word segment

    // Prologue: y(0) via cp.async
    {
        const __nv_bfloat16* src = g_yB + (size_t)(rg * 16 + pr) * H + ps * 32;
#pragma unroll
        for (int i = 0; i < 4; i++) {
            const int w0 = ps * 16 + 4 * i;
            cp16(smw + YOFF + pr * 256 + (w0 ^ ((pr & 7) << 2)), src + i * 8);
        }
        CP_COMMIT();
    }

    // w_ih -> SMEM bf16 with XOR swizzle (w_hh not stored in SMEM)
    for (int i = tid; i < 96 * 128; i += 256) {
        const int n = i >> 7, f4 = i & 127;
        const int tt = n >> 3;
        const int grow = (tt % 3) * H + dg * 32 + (tt / 3) * 8 + (n & 7);
        const float4 v = *(const float4*)(w_ih + (size_t)grow * H + f4 * 4);
        __nv_bfloat162 q0, q1;
        q0.x = __float2bfloat16_rn(v.x); q0.y = __float2bfloat16_rn(v.y);
        q1.x = __float2bfloat16_rn(v.z); q1.y = __float2bfloat16_rn(v.w);
        const int w0 = (f4 * 2) ^ ((n & 7) << 2);
        uint2 pk;
        pk.x = *(const uint32_t*)&q0;
        pk.y = *(const uint32_t*)&q1;
        *(uint2*)(smw + n * 256 + w0) = pk;
    }

    // Gate-phase setup: thread -> (row_e, dim pair j2)
    const int row_e = tid >> 4;
    const int j2 = (tid & 15) * 2;
    const int grow_e = rg * 16 + row_e;
    const int jg = dg * 32 + j2;
    float2 br2, bz2;
    {
        float2 a = *(const float2*)(b_ih + jg), b = *(const float2*)(b_hh + jg);
        br2 = make_float2(a.x + b.x, a.y + b.y);
        a = *(const float2*)(b_ih + H + jg); b = *(const float2*)(b_hh + H + jg);
        bz2 = make_float2(a.x + b.x, a.y + b.y);
    }
    const float2 bin2 = *(const float2*)(b_ih + 2 * H + jg);
    const float2 bhn2 = *(const float2*)(b_hh + 2 * H + jg);

    // Fragment bases
    const uint32_t* Yb0 = smw + YOFF + g * 256;
    const uint32_t* Yb1 = smw + YOFF + (g + 8) * 256;
    const uint32_t* Hb0 = smw + HOFF + g * 256;
    const uint32_t* Hb1 = smw + HOFF + (g + 8) * 256;
    const uint32_t* Wi0 = smw + (nt * 24 + g) * 256;
    const int xw = g << 2;
    const int kbase = kh * 128;

    // w_hh b-fragments -> registers, loaded DIRECTLY from global
    uint32_t breg[16][3][2];
#pragma unroll
    for (int nb = 0; nb < 3; nb++) {
        const float* wrow = w_hh + (size_t)(nb * H + dg * 32 + nt * 8 + g) * H;
#pragma unroll
        for (int ck = 0; ck < 16; ck++) {
#pragma unroll
            for (int q = 0; q < 2; q++) {
                const int k0 = 2 * (kbase + ck * 8 + tig + q * 4);
                __nv_bfloat162 pk;
                pk.x = __float2bfloat16_rn(wrow[k0]);
                pk.y = __float2bfloat16_rn(wrow[k0 + 1]);
                breg[ck][nb][q] = *(const uint32_t*)&pk;
            }
        }
    }

    __syncthreads();   // w_ih tile ready

    // w_ih b-fragments for the first NCACHE chunks (from SMEM)
    uint32_t bregI[NCACHE][3][2];
#pragma unroll
    for (int ck = 0; ck < NCACHE; ck++) {
        const int w = kbase + ck * 8 + tig;
        const int wx0 = w ^ xw;
        const int wx4 = (w + 4) ^ xw;
        bregI[ck][0][0] = Wi0[wx0];            bregI[ck][0][1] = Wi0[wx4];
        bregI[ck][1][0] = Wi0[8 * 256 + wx0];  bregI[ck][1][1] = Wi0[8 * 256 + wx4];
        bregI[ck][2][0] = Wi0[16 * 256 + wx0]; bregI[ck][2][1] = Wi0[16 * 256 + wx4];
    }

    float2 ho2 = make_float2(0.0f, 0.0f);   // h_old lives in registers
    int p = 0;
    for (int t = 0; t < L; t++) {
        const bool hasnext = (t + 1 < L);

        // ---- top: y(t) cp done (issued mid-previous-step -> long overlap) ----
        CP_WAIT0();
        __syncthreads();

        // ---- giA: chunks 0..7 of y(t) x w_ih (covers residual peer skew) ----
        float c0[4] = {}, c1[4] = {}, c2i[4] = {}, c2h[4] = {};
#pragma unroll
        for (int ck = 0; ck < NCACHE; ck++) {
            const int w = kbase + ck * 8 + tig;
            const int wx0 = w ^ xw;
            const int wx4 = (w + 4) ^ xw;
            uint32_t ay[4];
            ay[0] = Yb0[wx0]; ay[1] = Yb1[wx0]; ay[2] = Yb0[wx4]; ay[3] = Yb1[wx4];
            mma_bf16(c0, ay, bregI[ck][0]);
            mma_bf16(c1, ay, bregI[ck][1]);
            mma_bf16(c2i, ay, bregI[ck][2]);
        }
#pragma unroll
        for (int ck = NCACHE; ck < 8; ck++) {
            const int w = kbase + ck * 8 + tig;
            const int wx0 = w ^ xw;
            const int wx4 = (w + 4) ^ xw;
            uint32_t ay[4], bb[2];
            ay[0] = Yb0[wx0]; ay[1] = Yb1[wx0]; ay[2] = Yb0[wx4]; ay[3] = Yb1[wx4];
            bb[0] = Wi0[wx0]; bb[1] = Wi0[wx4];
            mma_bf16(c0, ay, bb);
            bb[0] = Wi0[8 * 256 + wx0]; bb[1] = Wi0[8 * 256 + wx4];
            mma_bf16(c1, ay, bb);
            bb[0] = Wi0[16 * 256 + wx0]; bb[1] = Wi0[16 * 256 + wx4];
            mma_bf16(c2i, ay, bb);
        }

        // ---- wait: all 16 peer flags >= t (parallel, contention-free) ----
        if (tid < GRP) {
            unsigned v;
            do {
                asm volatile("ld.acquire.gpu.u32 %0, [%1];"
                             : "=r"(v) : "l"(&g_flag[rg][tid][0]) : "memory");
            } while (v < (unsigned)t);
        }
        __syncthreads();

        // ---- cp h(t) tile; latency hides under giB ----
        {
            const __nv_bfloat16* src = g_hB[p] + (size_t)(rg * 16 + pr) * H + ps * 32;
#pragma unroll
            for (int i = 0; i < 4; i++) {
                const int w0 = ps * 16 + 4 * i;
                cp16(smw + HOFF + pr * 256 + (w0 ^ ((pr & 7) << 2)), src + i * 8);
            }
            CP_COMMIT();
        }

        // ---- giB: chunks 8..15 of y(t) x w_ih ----
#pragma unroll 4
        for (int ck = 8; ck < 16; ck++) {
            const int w = kbase + ck * 8 + tig;
            const int wx0 = w ^ xw;
            const int wx4 = (w + 4) ^ xw;
            uint32_t ay[4], bb[2];
            ay[0] = Yb0[wx0]; ay[1] = Yb1[wx0]; ay[2] = Yb0[wx4]; ay[3] = Yb1[wx4];
            bb[0] = Wi0[wx0]; bb[1] = Wi0[wx4];
            mma_bf16(c0, ay, bb);
            bb[0] = Wi0[8 * 256 + wx0]; bb[1] = Wi0[8 * 256 + wx4];
            mma_bf16(c1, ay, bb);
            bb[0] = Wi0[16 * 256 + wx0]; bb[1] = Wi0[16 * 256 + wx4];
            mma_bf16(c2i, ay, bb);
        }

        CP_WAIT0();
        __syncthreads();   // h tile complete + all gi y-tile reads done

        // ---- y(t+1) cp into y tile NOW: overlaps gh + Red + gates + release ----
        if (hasnext) {
            const __nv_bfloat16* src = g_yB + (size_t)((t + 1) * B + rg * 16 + pr) * H + ps * 32;
#pragma unroll
            for (int i = 0; i < 4; i++) {
                const int w0 = ps * 16 + 4 * i;
                cp16(smw + YOFF + pr * 256 + (w0 ^ ((pr & 7) << 2)), src + i * 8);
            }
        }
        CP_COMMIT();

        // ---- gh mma: h(t) x w_hh (weights from registers) ----
#pragma unroll
        for (int ck = 0; ck < 16; ck++) {
            const int w = kbase + ck * 8 + tig;
            const int wx0 = w ^ xw;
            const int wx4 = (w + 4) ^ xw;
            uint32_t ah[4];
            ah[0] = Hb0[wx0]; ah[1] = Hb1[wx0]; ah[2] = Hb0[wx4]; ah[3] = Hb1[wx4];
            mma_bf16(c0, ah, breg[ck][0]);
            mma_bf16(c1, ah, breg[ck][1]);
            mma_bf16(c2h, ah, breg[ck][2]);
        }

        // ---- Red write (dedicated region; warp-local, no pre-sync needed) ----
        {
            float* Ra = Red + kh * RPLANE + g * RLD;
            float* Rb = Red + kh * RPLANE + (g + 8) * RLD;
            const int n0 = nt * 24 + 2 * tig;
            const int nd = nt * 8 + 2 * tig;
            *(float2*)&Ra[n0] = make_float2(c0[0], c0[1]);
            *(float2*)&Rb[n0] = make_float2(c0[2], c0[3]);
            *(float2*)&Ra[n0 + 8] = make_float2(c1[0], c1[1]);
            *(float2*)&Rb[n0 + 8] = make_float2(c1[2], c1[3]);
            *(float2*)&Ra[96 + nd] = make_float2(c2i[0], c2i[1]);
            *(float2*)&Rb[96 + nd] = make_float2(c2i[2], c2i[3]);
            *(float2*)&Ra[128 + nd] = make_float2(c2h[0], c2h[1]);
            *(float2*)&Rb[128 + nd] = make_float2(c2h[2], c2h[3]);
        }
        __syncthreads();

        // ---- gates: fast-math nonlinearities; h_old from registers ----
        {
            const float* R0 = Red + row_e * RLD;
            const float* R1 = Red + RPLANE + row_e * RLD;
            const int rcol = (j2 >> 3) * 24 + (j2 & 7);
            const float2 rpa = *(const float2*)&R0[rcol],      rpb = *(const float2*)&R1[rcol];
            const float2 zpa = *(const float2*)&R0[rcol + 8],  zpb = *(const float2*)&R1[rcol + 8];
            const float2 nia = *(const float2*)&R0[96 + j2],   nib = *(const float2*)&R1[96 + j2];
            const float2 nha = *(const float2*)&R0[128 + j2],  nhb = *(const float2*)&R1[128 + j2];
            const float r0 = fast_sigmoid(rpa.x + rpb.x + br2.x);
            const float r1 = fast_sigmoid(rpa.y + rpb.y + br2.y);
            const float z0 = fast_sigmoid(zpa.x + zpb.x + bz2.x);
            const float z1 = fast_sigmoid(zpa.y + zpb.y + bz2.y);
            const float n0v = fast_tanh(nia.x + nib.x + bin2.x + r0 * (nha.x + nhb.x + bhn2.x));
            const float n1v = fast_tanh(nia.y + nib.y + bin2.y + r1 * (nha.y + nhb.y + bhn2.y));
            float2 hn;
            hn.x = (1.0f - z0) * n0v + z0 * ho2.x;
            hn.y = (1.0f - z1) * n1v + z1 * ho2.y;
            ho2 = hn;
            __nv_bfloat162 hb;
            hb.x = __float2bfloat16_rn(hn.x);
            hb.y = __float2bfloat16_rn(hn.y);
            *(__nv_bfloat162*)(g_hB[p ^ 1] + (size_t)grow_e * H + jg) = hb;
            if (t == L - 1) *(float2*)(g_h[0] + (size_t)grow_e * H + jg) = hn;
        }

        __syncthreads();   // h STG + Red reads done

        // ---- release: publish h(t+1) on this CTA's own flag ----
        if (tid == 0) {
            const unsigned tgt = (unsigned)(t + 1);
            asm volatile("st.release.gpu.global.u32 [%0], %1;"
                         :: "l"(&g_flag[rg][dg][0]), "r"(tgt) : "memory");
        }
        p ^= 1;
    }
}

// ---------------------------------------------------------------------------
// Classifier
// ---------------------------------------------------------------------------
__global__ void classifier_kernel(const float* __restrict__ cls_w,
                                  const float* __restrict__ cls_b,
                                  float* __restrict__ out) {
    const int b = blockIdx.x / C;
    const int cc = blockIdx.x % C;
    const float* h = g_h[0] + b * H;
    const float* w = cls_w + cc * H;
    float s = 0.0f;
    for (int k = threadIdx.x; k < H; k += 64) s += h[k] * w[k];
#pragma unroll
    for (int o = 16; o > 0; o >>= 1) s += __shfl_down_sync(0xffffffffu, s, o);
    __shared__ float red[2];
    if ((threadIdx.x & 31) == 0) red[threadIdx.x >> 5] = s;
    __syncthreads();
    if (threadIdx.x == 0) out[b * C + cc] = red[0] + red[1] + cls_b[cc];
}

// ---------------------------------------------------------------------------
// Launch
// ---------------------------------------------------------------------------
extern "C" void kernel_launch(void* const* d_in, const int* in_sizes, int n_in,
                              void* d_out, int out_size) {
    const int*   x      = (const int*)d_in[0];
    const float* conv_w = (const float*)d_in[1];
    const float* conv_b = (const float*)d_in[2];
    const float* w_ih   = (const float*)d_in[3];
    const float* w_hh   = (const float*)d_in[4];
    const float* b_ih   = (const float*)d_in[5];
    const float* b_hh   = (const float*)d_in[6];
    const float* cls_w  = (const float*)d_in[7];
    const float* cls_b  = (const float*)d_in[8];
    float* out = (float*)d_out;

    cudaFuncSetAttribute(gru_kernel, cudaFuncAttributeMaxDynamicSharedMemorySize, GRU_SMEM);

    init_kernel<<<512, 256>>>();
    prep_kernel<<<(H * V * 3 + 255) / 256, 256>>>(conv_w);
    embed_kernel<<<NROW, 128>>>(x, conv_b);
    gru_kernel<<<NGRP * GRP, 256, GRU_SMEM>>>(w_ih, w_hh, b_ih, b_hh);
    classifier_kernel<<<B * C, 64>>>(cls_w, cls_b, out);
}